// round 7
// baseline (speedup 1.0000x reference)
#include <cuda_runtime.h>
#include <mma.h>
#include <math.h>
#include <stdint.h>

using namespace nvcuda;

#define NQN 1000
#define NTN 100000
#define EQN 16000
#define ETN 800000
#define KVN 512
#define NMAP 200
#define D 128
#define DBIL 64
#define DMLP 192

// H buffers padded to 128-row tile multiples so wmma stores need no guards.
#define NQPAD 1024
#define NTPAD 100096

// ---------------- scratch (device globals: no allocation allowed) ----------------
__device__ float g_Hq[(size_t)NQPAD * D];
__device__ float g_Ht[(size_t)NTPAD * D];
__device__ float g_dinvq[NQN];
__device__ float g_dinvt[NTN];
__device__ int   g_cntq[NQN];
__device__ int   g_cntt[NTN];
__device__ int   g_rowq[NQN + 1];
__device__ int   g_rowt[NTN + 1];
__device__ int   g_colq[EQN];
__device__ int   g_colt[ETN];
__device__ float g_valq[EQN];
__device__ float g_valt[ETN];
__device__ int   g_partq[512];
__device__ int   g_partt[512];
__device__ float g_T[DBIL * D];
__device__ float g_feat[KVN * DMLP];

// ---------------- CSR build ----------------
__global__ void k_zeroi(int* p, int n) {
    int i = blockIdx.x * blockDim.x + threadIdx.x;
    if (i < n) p[i] = 0;
}

__global__ void k_hist(const int* __restrict__ dst, int* cnt, int E) {
    int e = blockIdx.x * blockDim.x + threadIdx.x;
    if (e < E) atomicAdd(&cnt[dst[e]], 1);
}

__global__ void k_partial(const int* __restrict__ cnt, int* __restrict__ part, int N) {
    int t = threadIdx.x;
    int i = blockIdx.x * 256 + t;
    int c = (i < N) ? cnt[i] : 0;
    int lane = t & 31, w = t >> 5;
#pragma unroll
    for (int o = 16; o > 0; o >>= 1) c += __shfl_xor_sync(0xFFFFFFFFu, c, o);
    __shared__ int s[8];
    if (lane == 0) s[w] = c;
    __syncthreads();
    if (t == 0) {
        int sum = 0;
#pragma unroll
        for (int j = 0; j < 8; j++) sum += s[j];
        part[blockIdx.x] = sum;
    }
}

__global__ void k_scanp(int* part, int nb) {
    __shared__ int s[512];
    int t = threadIdx.x;
    int v = (t < nb) ? part[t] : 0;
    s[t] = v;
    __syncthreads();
    for (int o = 1; o < 512; o <<= 1) {
        int u = (t >= o) ? s[t - o] : 0;
        __syncthreads();
        s[t] += u;
        __syncthreads();
    }
    if (t < nb) part[t] = s[t] - v;   // exclusive
}

__global__ void k_rowptr(const int* __restrict__ cnt, const int* __restrict__ poff,
                         int* __restrict__ rowptr, float* __restrict__ dinv, int N) {
    int t = threadIdx.x;
    int i = blockIdx.x * 256 + t;
    int c = (i < N) ? cnt[i] : 0;
    int lane = t & 31, w = t >> 5;
    int v = c;
#pragma unroll
    for (int o = 1; o < 32; o <<= 1) {
        int u = __shfl_up_sync(0xFFFFFFFFu, v, o);
        if (lane >= o) v += u;
    }
    __shared__ int ws[8];
    if (lane == 31) ws[w] = v;
    __syncthreads();
    if (t < 8) {
        int x = ws[t];
#pragma unroll
        for (int o = 1; o < 8; o <<= 1) {
            int u = __shfl_up_sync(0xFFu, x, o);
            if (t >= o) x += u;
        }
        ws[t] = x;
    }
    __syncthreads();
    int incl = v + ((w > 0) ? ws[w - 1] : 0);
    int off = poff[blockIdx.x];
    if (i < N) {
        rowptr[i] = off + incl - c;
        dinv[i] = rsqrtf((float)c + 1.f);
        if (i == N - 1) rowptr[N] = off + incl;
    }
}

__global__ void k_fill(const int* __restrict__ ei, const int* __restrict__ rowptr,
                       int* cursor, int* col, int E) {
    int e = blockIdx.x * blockDim.x + threadIdx.x;
    if (e >= E) return;
    int s = ei[e];
    int d = ei[E + e];
    int pos = rowptr[d] + atomicAdd(&cursor[d], 1);
    col[pos] = s;
}

// per-row sort by src (canonical -> deterministic fp32 sum order) + coef values
__global__ void k_rowfin(const int* __restrict__ rowptr, int* __restrict__ col,
                         float* __restrict__ val, const float* __restrict__ dinv, int N) {
    int r = blockIdx.x * blockDim.x + threadIdx.x;
    if (r >= N) return;
    int b = rowptr[r], e = rowptr[r + 1];
    for (int i = b + 1; i < e; i++) {
        int key = col[i];
        int j = i - 1;
        while (j >= b && col[j] > key) { col[j + 1] = col[j]; j--; }
        col[j + 1] = key;
    }
    float dr = dinv[r];
    for (int i = b; i < e; i++) val[i] = dinv[col[i]] * dr;
}

// ---------------- TF32 wmma GEMM (3xTF32 compensation) ----------------
// H[N,128] = X[N,128] @ W[128,128]. Block tile 128x128, 8 warps (2x4),
// warp tile 64x32 = 4x2 wmma m16n16k8 tiles. H padded so stores are unguarded.
#define BLDM 136   // B smem leading dim (multiple of 8)

__global__ void __launch_bounds__(256)
k_gemm_tc(const float* __restrict__ X, const float* __restrict__ W,
          float* __restrict__ H, int N) {
    __shared__ float Ah[128][16], Al[128][16];
    __shared__ float Bh[16][BLDM], Bl[16][BLDM];

    int t = threadIdx.x;
    int warp = t >> 5;
    int wr = warp >> 2;        // 0..1 : row group (64 rows)
    int wc = warp & 3;         // 0..3 : col group (32 cols)
    int row0 = blockIdx.x * 128;

    wmma::fragment<wmma::accumulator, 16, 16, 8, float> acc[4][2];
#pragma unroll
    for (int mi = 0; mi < 4; mi++)
#pragma unroll
        for (int ni = 0; ni < 2; ni++) wmma::fill_fragment(acc[mi][ni], 0.f);

    for (int k0 = 0; k0 < 128; k0 += 16) {
        // A chunk 128x16, split hi/lo (Dekker)
#pragma unroll
        for (int j = 0; j < 2; j++) {
            int fi = t + 256 * j;          // 0..511 float4s
            int r = fi >> 2;
            int kc = (fi & 3) * 4;
            int gr = row0 + r;
            float4 v = make_float4(0.f, 0.f, 0.f, 0.f);
            if (gr < N) v = *(const float4*)(X + (size_t)gr * D + k0 + kc);
            float h0 = wmma::__float_to_tf32(v.x), h1 = wmma::__float_to_tf32(v.y);
            float h2 = wmma::__float_to_tf32(v.z), h3 = wmma::__float_to_tf32(v.w);
            Ah[r][kc] = h0; Ah[r][kc + 1] = h1; Ah[r][kc + 2] = h2; Ah[r][kc + 3] = h3;
            Al[r][kc]     = wmma::__float_to_tf32(v.x - h0);
            Al[r][kc + 1] = wmma::__float_to_tf32(v.y - h1);
            Al[r][kc + 2] = wmma::__float_to_tf32(v.z - h2);
            Al[r][kc + 3] = wmma::__float_to_tf32(v.w - h3);
        }
        // B chunk 16x128 (row-major k x n), split hi/lo
#pragma unroll
        for (int j = 0; j < 2; j++) {
            int fi = t + 256 * j;
            int k = fi >> 5;               // 0..15
            int nc = (fi & 31) * 4;        // 0..124
            float4 v = *(const float4*)(W + (size_t)(k0 + k) * D + nc);
            float h0 = wmma::__float_to_tf32(v.x), h1 = wmma::__float_to_tf32(v.y);
            float h2 = wmma::__float_to_tf32(v.z), h3 = wmma::__float_to_tf32(v.w);
            Bh[k][nc] = h0; Bh[k][nc + 1] = h1; Bh[k][nc + 2] = h2; Bh[k][nc + 3] = h3;
            Bl[k][nc]     = wmma::__float_to_tf32(v.x - h0);
            Bl[k][nc + 1] = wmma::__float_to_tf32(v.y - h1);
            Bl[k][nc + 2] = wmma::__float_to_tf32(v.z - h2);
            Bl[k][nc + 3] = wmma::__float_to_tf32(v.w - h3);
        }
        __syncthreads();

#pragma unroll
        for (int ks = 0; ks < 16; ks += 8) {
            wmma::fragment<wmma::matrix_b, 16, 16, 8, wmma::precision::tf32, wmma::row_major> fbh[2], fbl[2];
#pragma unroll
            for (int ni = 0; ni < 2; ni++) {
                wmma::load_matrix_sync(fbh[ni], &Bh[ks][wc * 32 + ni * 16], BLDM);
                wmma::load_matrix_sync(fbl[ni], &Bl[ks][wc * 32 + ni * 16], BLDM);
            }
#pragma unroll
            for (int mi = 0; mi < 4; mi++) {
                wmma::fragment<wmma::matrix_a, 16, 16, 8, wmma::precision::tf32, wmma::row_major> fah, fal;
                wmma::load_matrix_sync(fah, &Ah[wr * 64 + mi * 16][ks], 16);
                wmma::load_matrix_sync(fal, &Al[wr * 64 + mi * 16][ks], 16);
#pragma unroll
                for (int ni = 0; ni < 2; ni++) {
                    wmma::mma_sync(acc[mi][ni], fah, fbh[ni], acc[mi][ni]);  // hi*hi
                    wmma::mma_sync(acc[mi][ni], fal, fbh[ni], acc[mi][ni]);  // lo*hi
                    wmma::mma_sync(acc[mi][ni], fah, fbl[ni], acc[mi][ni]);  // hi*lo
                }
            }
        }
        __syncthreads();
    }

    // unguarded stores into padded H
#pragma unroll
    for (int mi = 0; mi < 4; mi++)
#pragma unroll
        for (int ni = 0; ni < 2; ni++) {
            int r = row0 + wr * 64 + mi * 16;
            int c = wc * 32 + ni * 16;
            wmma::store_matrix_sync(H + (size_t)r * D + c, acc[mi][ni], D, wmma::mem_row_major);
        }
}

// ---------------- fused aggregation + self-loop + bias + l2norm (+elu) ----------------
__global__ void k_agg(const float* __restrict__ H, const int* __restrict__ rowptr,
                      const int* __restrict__ col, const float* __restrict__ val,
                      const float* __restrict__ dinv, const float* __restrict__ bias,
                      float* __restrict__ X, int N, int elu) {
    int idx = blockIdx.x * blockDim.x + threadIdx.x;
    int row = idx >> 5;
    if (row >= N) return;
    int lane = idx & 31;

    float s = dinv[row]; s *= s;
    float4 h = __ldg(&((const float4*)(H + (size_t)row * D))[lane]);
    float4 b = __ldg(&((const float4*)bias)[lane]);
    float ax = fmaf(h.x, s, b.x);
    float ay = fmaf(h.y, s, b.y);
    float az = fmaf(h.z, s, b.z);
    float aw = fmaf(h.w, s, b.w);

    int beg = rowptr[row], end = rowptr[row + 1];
    int j = beg;
    for (; j + 2 <= end; j += 2) {
        int s0 = col[j], s1 = col[j + 1];
        float c0 = val[j], c1 = val[j + 1];
        float4 v0 = __ldg(&((const float4*)(H + (size_t)s0 * D))[lane]);
        float4 v1 = __ldg(&((const float4*)(H + (size_t)s1 * D))[lane]);
        ax = fmaf(c0, v0.x, ax); ay = fmaf(c0, v0.y, ay);
        az = fmaf(c0, v0.z, az); aw = fmaf(c0, v0.w, aw);
        ax = fmaf(c1, v1.x, ax); ay = fmaf(c1, v1.y, ay);
        az = fmaf(c1, v1.z, az); aw = fmaf(c1, v1.w, aw);
    }
    if (j < end) {
        int s0 = col[j];
        float c0 = val[j];
        float4 v0 = __ldg(&((const float4*)(H + (size_t)s0 * D))[lane]);
        ax = fmaf(c0, v0.x, ax); ay = fmaf(c0, v0.y, ay);
        az = fmaf(c0, v0.z, az); aw = fmaf(c0, v0.w, aw);
    }

    float ss = ax * ax + ay * ay + az * az + aw * aw;
#pragma unroll
    for (int o = 16; o > 0; o >>= 1) ss += __shfl_xor_sync(0xFFFFFFFFu, ss, o);
    float inv = 1.f / fmaxf(sqrtf(ss), 1e-12f);
    ax *= inv; ay *= inv; az *= inv; aw *= inv;
    if (elu) {
        ax = ax > 0.f ? ax : expm1f(ax);
        ay = ay > 0.f ? ay : expm1f(ay);
        az = az > 0.f ? az : expm1f(az);
        aw = aw > 0.f ? aw : expm1f(aw);
    }
    ((float4*)(X + (size_t)row * D))[lane] = make_float4(ax, ay, az, aw);
}

// ---------------- consensus ----------------
__global__ void k_cons(const float* __restrict__ Xq, float* __restrict__ Xt,
                       const int* __restrict__ umap, const int* __restrict__ vmap) {
    int idx = blockIdx.x * blockDim.x + threadIdx.x;
    int row = idx >> 5, lane = idx & 31;
    if (row >= NMAP) return;
    int us = umap[row], vd = vmap[row];
    ((float4*)(Xt + (size_t)vd * D))[lane] = ((const float4*)(Xq + (size_t)us * D))[lane];
}

// ---------------- bilinear stage A ----------------
__global__ void k_bilinA(const float* __restrict__ Xq, const int* __restrict__ u_ptr,
                         const float* __restrict__ Wb, float* __restrict__ T) {
    __shared__ float a[D];
    int o = blockIdx.x;
    int k = threadIdx.x;
    int u = *u_ptr;
    a[k] = Xq[(size_t)u * D + k];
    __syncthreads();
    const float* w = Wb + (size_t)o * D * D + k;
    float acc = 0.f;
#pragma unroll 8
    for (int j = 0; j < D; j++) acc = fmaf(a[j], w[(size_t)j * D], acc);
    T[o * D + k] = acc;
}

// ---------------- bilinear stage B ----------------
__global__ void k_bilinB(const float* __restrict__ T, const float* __restrict__ Xt,
                         const int* __restrict__ v_li, const float* __restrict__ bb,
                         float* __restrict__ feat, int col0) {
    __shared__ float x[D];
    int v = blockIdx.x;
    int t = threadIdx.x;
    int vv = v_li[v];
    x[t] = Xt[(size_t)vv * D + t];
    x[t + 64] = Xt[(size_t)vv * D + 64 + t];
    __syncthreads();
    const float* tr = T + t * D;
    float acc = bb[t];
#pragma unroll 8
    for (int k = 0; k < D; k++) acc = fmaf(tr[k], x[k], acc);
    feat[v * DMLP + col0 + t] = acc;
}

// ---------------- MLP head ----------------
__global__ void k_mlp(const float* __restrict__ feat,
                      const float* __restrict__ W1, const float* __restrict__ b1,
                      const float* __restrict__ W2, const float* __restrict__ b2,
                      const float* __restrict__ W3, const float* __restrict__ b3,
                      float* __restrict__ out) {
    __shared__ float f[DMLP];
    __shared__ float h1[96];
    __shared__ float h2[48];
    int v = blockIdx.x;
    int t = threadIdx.x;
    f[t] = feat[v * DMLP + t];
    f[t + 96] = feat[v * DMLP + 96 + t];
    __syncthreads();
    float acc = b1[t];
#pragma unroll 8
    for (int j = 0; j < DMLP; j++) acc = fmaf(f[j], W1[j * 96 + t], acc);
    h1[t] = fmaxf(acc, 0.f);
    __syncthreads();
    if (t < 48) {
        float a2 = b2[t];
#pragma unroll 8
        for (int j = 0; j < 96; j++) a2 = fmaf(h1[j], W2[j * 48 + t], a2);
        h2[t] = fmaxf(a2, 0.f);
    }
    __syncthreads();
    if (t == 0) {
        float s = b3[0];
#pragma unroll
        for (int j = 0; j < 48; j++) s = fmaf(h2[j], W3[j], s);
        out[v] = s;
    }
}

// ---------------- launch ----------------
extern "C" void kernel_launch(void* const* d_in, const int* in_sizes, int n_in,
                              void* d_out, int out_size) {
    const float* x_q  = (const float*)d_in[0];
    const float* x_t  = (const float*)d_in[1];
    const int*   eiq  = (const int*)d_in[2];
    const int*   eit  = (const int*)d_in[3];
    const int*   u    = (const int*)d_in[4];
    const int*   v_li = (const int*)d_in[5];
    const int*   umap = (const int*)d_in[6];
    const int*   vmap = (const int*)d_in[7];
    const float* Wg   = (const float*)d_in[8];
    const float* bg   = (const float*)d_in[9];
    const float* Wb   = (const float*)d_in[10];
    const float* bb   = (const float*)d_in[11];
    const float* W1   = (const float*)d_in[12];
    const float* b1   = (const float*)d_in[13];
    const float* W2   = (const float*)d_in[14];
    const float* b2   = (const float*)d_in[15];
    const float* W3   = (const float*)d_in[16];
    const float* b3   = (const float*)d_in[17];

    float* out = (float*)d_out;
    float* Xq  = out + KVN;
    float* Xt  = Xq + (size_t)NQN * D;

    float *Hq, *Ht, *dq, *dt, *vq, *vt, *T, *feat;
    int *cq, *ct, *rq, *rt, *colq, *colt, *pq, *pt;
    cudaGetSymbolAddress((void**)&Hq, g_Hq);
    cudaGetSymbolAddress((void**)&Ht, g_Ht);
    cudaGetSymbolAddress((void**)&dq, g_dinvq);
    cudaGetSymbolAddress((void**)&dt, g_dinvt);
    cudaGetSymbolAddress((void**)&cq, g_cntq);
    cudaGetSymbolAddress((void**)&ct, g_cntt);
    cudaGetSymbolAddress((void**)&rq, g_rowq);
    cudaGetSymbolAddress((void**)&rt, g_rowt);
    cudaGetSymbolAddress((void**)&colq, g_colq);
    cudaGetSymbolAddress((void**)&colt, g_colt);
    cudaGetSymbolAddress((void**)&vq, g_valq);
    cudaGetSymbolAddress((void**)&vt, g_valt);
    cudaGetSymbolAddress((void**)&pq, g_partq);
    cudaGetSymbolAddress((void**)&pt, g_partt);
    cudaGetSymbolAddress((void**)&T, g_T);
    cudaGetSymbolAddress((void**)&feat, g_feat);

    const int TB = 256;
    const int NBQ = (NQN + 255) / 256;   // 4
    const int NBT = (NTN + 255) / 256;   // 391

    // ---- CSR build (graph-static, once per launch) ----
    k_zeroi<<<(NQN + TB - 1) / TB, TB>>>(cq, NQN);
    k_zeroi<<<(NTN + TB - 1) / TB, TB>>>(ct, NTN);
    k_hist<<<(EQN + TB - 1) / TB, TB>>>(eiq + EQN, cq, EQN);
    k_hist<<<(ETN + TB - 1) / TB, TB>>>(eit + ETN, ct, ETN);
    k_partial<<<NBQ, 256>>>(cq, pq, NQN);
    k_partial<<<NBT, 256>>>(ct, pt, NTN);
    k_scanp<<<1, 512>>>(pq, NBQ);
    k_scanp<<<1, 512>>>(pt, NBT);
    k_rowptr<<<NBQ, 256>>>(cq, pq, rq, dq, NQN);
    k_rowptr<<<NBT, 256>>>(ct, pt, rt, dt, NTN);
    k_zeroi<<<(NQN + TB - 1) / TB, TB>>>(cq, NQN);
    k_zeroi<<<(NTN + TB - 1) / TB, TB>>>(ct, NTN);
    k_fill<<<(EQN + TB - 1) / TB, TB>>>(eiq, rq, cq, colq, EQN);
    k_fill<<<(ETN + TB - 1) / TB, TB>>>(eit, rt, ct, colt, ETN);
    k_rowfin<<<(NQN + TB - 1) / TB, TB>>>(rq, colq, vq, dq, NQN);
    k_rowfin<<<(NTN + TB - 1) / TB, TB>>>(rt, colt, vt, dt, NTN);

    for (int i = 0; i < 3; i++) {
        const float* Wi = Wg + (size_t)i * D * D;
        const float* bi = bg + (size_t)i * D;
        const float* Xq_in = (i == 0) ? x_q : Xq;
        const float* Xt_in = (i == 0) ? x_t : Xt;
        int elu = (i < 2) ? 1 : 0;

        k_gemm_tc<<<(NQN + 127) / 128, 256>>>(Xq_in, Wi, Hq, NQN);
        k_gemm_tc<<<(NTN + 127) / 128, 256>>>(Xt_in, Wi, Ht, NTN);

        k_agg<<<((NQN * 32) + TB - 1) / TB, TB>>>(Hq, rq, colq, vq, dq, bi, Xq, NQN, elu);
        k_agg<<<((size_t)(NTN) * 32 + TB - 1) / TB, TB>>>(Ht, rt, colt, vt, dt, bi, Xt, NTN, elu);

        k_cons<<<(NMAP * 32 + TB - 1) / TB, TB>>>(Xq, Xt, umap, vmap);

        k_bilinA<<<DBIL, D>>>(Xq, u, Wb + (size_t)i * DBIL * D * D, T);
        k_bilinB<<<KVN, DBIL>>>(T, Xt, v_li, bb + (size_t)i * DBIL, feat, i * DBIL);
    }

    k_mlp<<<KVN, 96>>>(feat, W1, b1, W2, b2, W3, b3, out);
}